// round 1
// baseline (speedup 1.0000x reference)
#include <cuda_runtime.h>
#include <cuda_bf16.h>

// ---------------- problem constants ----------------
#define H_IN   132
#define W_IN   132
#define C_IN   256
#define N_B    2
#define HO     128
#define WO     128
#define NP     (HO*WO)          // 16384 pixels per image
#define KKN    9                // 3x3 taps
#define DILX   2
#define GRP    4
#define CG     64               // channels per group
#define KDIM   (C_IN*KKN)       // 2304
#define M_OFF  72
#define M_OUT  256

// ---------------- scratch (device globals; no runtime allocation) ----------------
// g_col: used first as im2col(X) [n][ci*9+k][p], then overwritten with the
// bilinear-sampled matrix [n][(g*64+c)*9+k][p]. 2*2304*16384 floats = 302MB.
__device__ float g_col[(size_t)N_B * KDIM * NP];
// offsets from GEMM1: [n][72][p]
__device__ float g_off[(size_t)N_B * M_OFF * NP];

// ---------------- kernel 1: im2col for the offset conv ----------------
// Xcol[n][ci*9+k][ho*128+wo] = x[n][ci][ho+2*ky][wo+2*kx]
__global__ void gather_xcol(const float* __restrict__ x) {
    int row = blockIdx.y;                       // 0..KDIM-1
    int n   = blockIdx.z;
    int p4  = (blockIdx.x * blockDim.x + threadIdx.x) * 4;   // pixel, step 4
    int ci  = row / KKN;
    int k   = row % KKN;
    int ky  = k / 3, kx = k % 3;
    int ho  = p4 >> 7;
    int wo  = p4 & 127;
    const float* src = x + (((size_t)n * C_IN + ci) * H_IN + (ho + DILX * ky)) * W_IN
                         + (wo + DILX * kx);
    float4 v = make_float4(src[0], src[1], src[2], src[3]);
    *reinterpret_cast<float4*>(g_col + ((size_t)n * KDIM + row) * NP + p4) = v;
}

// ---------------- kernel 2: bilinear sampled matrix ----------------
// For each (n,g,k,p): compute sampling position from offsets once, reuse the
// 4 indices / weights across all 64 group channels.
__global__ void gather_sampled(const float* __restrict__ x) {
    int n  = blockIdx.z;
    int gk = blockIdx.y;                 // 0..35
    int g  = gk / KKN, k = gk % KKN;
    int p  = blockIdx.x * blockDim.x + threadIdx.x;
    int ho = p >> 7, wo = p & 127;
    int ky = k / 3, kx = k % 3;

    const float* offbase = g_off + ((size_t)n * M_OFF + g * 18 + k * 2) * NP + p;
    float dy = offbase[0];
    float dx = offbase[NP];

    float yf = dy + (float)(ky * DILX + ho);
    float xf = dx + (float)(kx * DILX + wo);
    float y0f = floorf(yf), x0f = floorf(xf);
    float ly = yf - y0f, lx = xf - x0f;
    int y0 = (int)y0f, x0 = (int)x0f;
    int y1 = y0 + 1,  x1 = x0 + 1;

    float w00 = (1.f - ly) * (1.f - lx);
    float w01 = (1.f - ly) * lx;
    float w10 = ly * (1.f - lx);
    float w11 = ly * lx;

    bool vy0 = (y0 >= 0) & (y0 < H_IN);
    bool vy1 = (y1 >= 0) & (y1 < H_IN);
    bool vx0 = (x0 >= 0) & (x0 < W_IN);
    bool vx1 = (x1 >= 0) & (x1 < W_IN);
    w00 *= (float)(vy0 & vx0);
    w01 *= (float)(vy0 & vx1);
    w10 *= (float)(vy1 & vx0);
    w11 *= (float)(vy1 & vx1);

    int cy0 = min(max(y0, 0), H_IN - 1);
    int cy1 = min(max(y1, 0), H_IN - 1);
    int cx0 = min(max(x0, 0), W_IN - 1);
    int cx1 = min(max(x1, 0), W_IN - 1);
    int i00 = cy0 * W_IN + cx0;
    int i01 = cy0 * W_IN + cx1;
    int i10 = cy1 * W_IN + cx0;
    int i11 = cy1 * W_IN + cx1;

    const float* xb = x + ((size_t)n * C_IN + g * CG) * (H_IN * W_IN);
    float* outb = g_col + ((size_t)n * KDIM + (size_t)(g * CG) * KKN + k) * NP + p;

    #pragma unroll 4
    for (int c = 0; c < CG; ++c) {
        const float* xc = xb + c * (H_IN * W_IN);
        float v = w00 * __ldg(xc + i00) + w01 * __ldg(xc + i01)
                + w10 * __ldg(xc + i10) + w11 * __ldg(xc + i11);
        outb[(size_t)c * (KKN * NP)] = v;
    }
}

// ---------------- kernel 3: SGEMM C[n] = A[M,K] * g_col[n][K,NP] (+bias) ----------------
// 128x128 block tile, BK=8, 256 threads, 8x8 per-thread microtile.
// If Cout == nullptr, writes to g_off (GEMM1); else writes to Cout (GEMM2).
__global__ void __launch_bounds__(256)
sgemm128(const float* __restrict__ A, float* __restrict__ Cout,
         const float* __restrict__ bias, int M)
{
    const int K = KDIM, N = NP;
    __shared__ float As[8][128];
    __shared__ float Bs[8][128];

    int n  = blockIdx.z;
    int bx = blockIdx.x * 128;      // N offset
    int by = blockIdx.y * 128;      // M offset
    int tid = threadIdx.x;
    int ty = tid >> 4;              // 0..15
    int tx = tid & 15;              // 0..15

    const float* Bn = g_col + (size_t)n * K * N;
    float* Cn = (Cout ? Cout : g_off) + (size_t)n * M * N;

    // A load mapping: each thread loads one float4 along K
    int ar    = tid >> 1;           // 0..127 (row within tile)
    int acol4 = (tid & 1) * 4;      // 0 or 4
    int arow  = by + ar;
    // B load mapping: each thread loads one float4 along N
    int brow  = tid >> 5;           // 0..7
    int bcol  = (tid & 31) * 4;     // 0..124

    const bool active = (by + ty * 8) < M;   // whole 8-row microtile out of range?

    float acc[8][8];
    #pragma unroll
    for (int i = 0; i < 8; ++i)
        #pragma unroll
        for (int j = 0; j < 8; ++j) acc[i][j] = 0.f;

    for (int kt = 0; kt < K; kt += 8) {
        // load A tile (transposed into As[k][m])
        float4 a4 = make_float4(0.f, 0.f, 0.f, 0.f);
        if (arow < M)
            a4 = *reinterpret_cast<const float4*>(A + (size_t)arow * K + kt + acol4);
        As[acol4 + 0][ar] = a4.x;
        As[acol4 + 1][ar] = a4.y;
        As[acol4 + 2][ar] = a4.z;
        As[acol4 + 3][ar] = a4.w;
        // load B tile
        float4 b4 = *reinterpret_cast<const float4*>(Bn + (size_t)(kt + brow) * N + bx + bcol);
        *reinterpret_cast<float4*>(&Bs[brow][bcol]) = b4;
        __syncthreads();

        if (active) {
            #pragma unroll
            for (int kk = 0; kk < 8; ++kk) {
                float4 a0 = *reinterpret_cast<const float4*>(&As[kk][ty * 8]);
                float4 a1 = *reinterpret_cast<const float4*>(&As[kk][ty * 8 + 4]);
                float4 b0 = *reinterpret_cast<const float4*>(&Bs[kk][tx * 8]);
                float4 b1 = *reinterpret_cast<const float4*>(&Bs[kk][tx * 8 + 4]);
                float ra[8] = {a0.x, a0.y, a0.z, a0.w, a1.x, a1.y, a1.z, a1.w};
                float rb[8] = {b0.x, b0.y, b0.z, b0.w, b1.x, b1.y, b1.z, b1.w};
                #pragma unroll
                for (int i = 0; i < 8; ++i)
                    #pragma unroll
                    for (int j = 0; j < 8; ++j)
                        acc[i][j] = fmaf(ra[i], rb[j], acc[i][j]);
            }
        }
        __syncthreads();
    }

    if (!active) return;
    #pragma unroll
    for (int i = 0; i < 8; ++i) {
        int row = by + ty * 8 + i;
        if (row >= M) break;
        float bv = bias ? bias[row] : 0.f;
        float4 o0 = make_float4(acc[i][0] + bv, acc[i][1] + bv, acc[i][2] + bv, acc[i][3] + bv);
        float4 o1 = make_float4(acc[i][4] + bv, acc[i][5] + bv, acc[i][6] + bv, acc[i][7] + bv);
        float* cp = Cn + (size_t)row * N + bx + tx * 8;
        *reinterpret_cast<float4*>(cp)     = o0;
        *reinterpret_cast<float4*>(cp + 4) = o1;
    }
}

// ---------------- launch ----------------
extern "C" void kernel_launch(void* const* d_in, const int* in_sizes, int n_in,
                              void* d_out, int out_size) {
    const float* x    = (const float*)d_in[0];   // (2,256,132,132)
    const float* offw = (const float*)d_in[1];   // (72,256,3,3)
    const float* offb = (const float*)d_in[2];   // (72,)
    const float* dw   = (const float*)d_in[3];   // (256,256,3,3)
    float* out = (float*)d_out;                  // (2,256,128,128)

    // 1) im2col of x
    {
        dim3 grid(NP / (256 * 4), KDIM, N_B);    // (16, 2304, 2)
        gather_xcol<<<grid, 256>>>(x);
    }
    // 2) offset = offw @ Xcol + bias     (M=72)
    {
        dim3 grid(NP / 128, 1, N_B);             // (128, 1, 2)
        sgemm128<<<grid, 256>>>(offw, nullptr, offb, M_OFF);
    }
    // 3) bilinear sampled matrix (overwrites g_col)
    {
        dim3 grid(NP / 256, GRP * KKN, N_B);     // (64, 36, 2)
        gather_sampled<<<grid, 256>>>(x);
    }
    // 4) out = dw @ sampled               (M=256)
    {
        dim3 grid(NP / 128, M_OUT / 128, N_B);   // (128, 2, 2)
        sgemm128<<<grid, 256>>>(dw, out, nullptr, M_OUT);
    }
}

// round 2
// speedup vs baseline: 1.2190x; 1.2190x over previous
#include <cuda_runtime.h>
#include <cuda_bf16.h>

// ---------------- problem constants ----------------
#define H_IN   132
#define W_IN   132
#define C_IN   256
#define N_B    2
#define HO     128
#define WO     128
#define NP     (HO*WO)          // 16384 pixels per image
#define KKN    9                // 3x3 taps
#define GRP    4
#define CG     64               // channels per group
#define KDIM   (C_IN*KKN)       // 2304
#define M_OFF  72
#define M_OUT  256

typedef unsigned long long ULL;

// ---------------- scratch (device globals) ----------------
__device__ float g_col[(size_t)N_B * KDIM * NP];   // bilinear-sampled matrix
__device__ float g_off[(size_t)N_B * M_OFF * NP];  // offsets from GEMM1

// ---------------- packed-fp32 helpers ----------------
__device__ __forceinline__ ULL dup2(float v) {
    ULL r; asm("mov.b64 %0, {%1, %1};" : "=l"(r) : "f"(v)); return r;
}
__device__ __forceinline__ void ffma2(ULL& d, ULL a, ULL b) {
    asm("fma.rn.f32x2 %0, %1, %2, %0;" : "+l"(d) : "l"(a), "l"(b));
}
__device__ __forceinline__ float2 u2f(ULL v) {
    float2 f; asm("mov.b64 {%0, %1}, %2;" : "=f"(f.x), "=f"(f.y) : "l"(v)); return f;
}

// ---------------- SGEMM: C[n] = A[M,K] @ B[n][K,NP] (+bias) ----------------
// 128x128 tile, BK=8, 256 threads, 8x8 microtile done as 8x(4 f32x2).
// BX=true : B is implicit im2col of x (GEMM1, output -> g_off)
// BX=false: B is g_col (GEMM2, output -> C)
template<bool BX>
__global__ void __launch_bounds__(256, 2)
sgemm128(const float* __restrict__ A, const float* __restrict__ xin,
         float* __restrict__ C, const float* __restrict__ bias, int M)
{
    __shared__ float As[2][8][128];
    __shared__ float Bs[2][8][128];

    const int n   = blockIdx.z;
    const int bx  = blockIdx.x * 128;    // N offset (== pixel row ho*128)
    const int by  = blockIdx.y * 128;    // M offset
    const int ho  = blockIdx.x;          // output row (BX path)
    const int tid = threadIdx.x;
    const int ty  = tid >> 4;            // 0..15
    const int tx  = tid & 15;            // 0..15

    const int ar    = tid >> 1;          // A row in tile
    const int acol4 = (tid & 1) * 4;     // A k-offset (0 or 4)
    const int arow  = by + ar;
    const int brow  = tid >> 5;          // B k-row (0..7)
    const int bcol  = (tid & 31) * 4;    // B n-col (0..124)

    const float* Bn = g_col + (size_t)n * KDIM * NP;   // used when !BX
    float* Cn = (BX ? g_off : C) + (size_t)n * M * NP;

    const bool aval   = (arow < M);
    const bool active = (by + ty * 8) < M;

    ULL acc[8][4];
    #pragma unroll
    for (int i = 0; i < 8; ++i) { acc[i][0]=0; acc[i][1]=0; acc[i][2]=0; acc[i][3]=0; }

    auto loadA = [&](int kt) -> float4 {
        if (!aval) return make_float4(0.f, 0.f, 0.f, 0.f);
        return *reinterpret_cast<const float4*>(A + (size_t)arow * KDIM + kt + acol4);
    };
    auto loadB = [&](int kt) -> float4 {
        if (!BX)
            return *reinterpret_cast<const float4*>(Bn + (size_t)(kt + brow) * NP + bx + bcol);
        int row = kt + brow;
        int ci  = row / 9;
        int k   = row - ci * 9;
        int ky  = k / 3;
        int kx  = k - ky * 3;
        const float* src = xin + (((size_t)n * C_IN + ci) * H_IN + (ho + 2 * ky)) * W_IN
                               + 2 * kx + bcol;
        float2 v0 = *reinterpret_cast<const float2*>(src);
        float2 v1 = *reinterpret_cast<const float2*>(src + 2);
        return make_float4(v0.x, v0.y, v1.x, v1.y);
    };
    auto stA = [&](int b, float4 v) {
        As[b][acol4 + 0][ar] = v.x; As[b][acol4 + 1][ar] = v.y;
        As[b][acol4 + 2][ar] = v.z; As[b][acol4 + 3][ar] = v.w;
    };
    auto stB = [&](int b, float4 v) {
        *reinterpret_cast<float4*>(&Bs[b][brow][bcol]) = v;
    };

    stA(0, loadA(0));
    stB(0, loadB(0));
    __syncthreads();

    int buf = 0;
    for (int kt = 8; kt <= KDIM; kt += 8) {
        float4 pa, pb;
        const bool more = (kt < KDIM);
        if (more) { pa = loadA(kt); pb = loadB(kt); }

        if (active) {
            #pragma unroll
            for (int kk = 0; kk < 8; ++kk) {
                float4 a0 = *reinterpret_cast<const float4*>(&As[buf][kk][ty * 8]);
                float4 a1 = *reinterpret_cast<const float4*>(&As[buf][kk][ty * 8 + 4]);
                const ulonglong2* bp =
                    reinterpret_cast<const ulonglong2*>(&Bs[buf][kk][tx * 8]);
                ulonglong2 q0 = bp[0];
                ulonglong2 q1 = bp[1];
                float av[8] = {a0.x, a0.y, a0.z, a0.w, a1.x, a1.y, a1.z, a1.w};
                #pragma unroll
                for (int i = 0; i < 8; ++i) {
                    ULL ad = dup2(av[i]);
                    ffma2(acc[i][0], ad, q0.x);
                    ffma2(acc[i][1], ad, q0.y);
                    ffma2(acc[i][2], ad, q1.x);
                    ffma2(acc[i][3], ad, q1.y);
                }
            }
        }

        if (more) {
            stA(buf ^ 1, pa);
            stB(buf ^ 1, pb);
            __syncthreads();
            buf ^= 1;
        }
    }

    if (!active) return;
    #pragma unroll
    for (int i = 0; i < 8; ++i) {
        int row = by + ty * 8 + i;
        float bv = bias ? bias[row] : 0.f;
        float2 f0 = u2f(acc[i][0]);
        float2 f1 = u2f(acc[i][1]);
        float2 f2 = u2f(acc[i][2]);
        float2 f3 = u2f(acc[i][3]);
        float4 o0 = make_float4(f0.x + bv, f0.y + bv, f1.x + bv, f1.y + bv);
        float4 o1 = make_float4(f2.x + bv, f2.y + bv, f3.x + bv, f3.y + bv);
        float* cp = Cn + (size_t)row * NP + bx + tx * 8;
        *reinterpret_cast<float4*>(cp)     = o0;
        *reinterpret_cast<float4*>(cp + 4) = o1;
    }
}

// ---------------- bilinear sampled matrix ----------------
__global__ void gather_sampled(const float* __restrict__ x) {
    int n  = blockIdx.z;
    int gk = blockIdx.y;                 // 0..35
    int g  = gk / KKN, k = gk % KKN;
    int p  = blockIdx.x * blockDim.x + threadIdx.x;
    int ho = p >> 7, wo = p & 127;
    int ky = k / 3, kx = k % 3;

    const float* offbase = g_off + ((size_t)n * M_OFF + g * 18 + k * 2) * NP + p;
    float dy = offbase[0];
    float dx = offbase[NP];

    float yf = dy + (float)(ky * 2 + ho);
    float xf = dx + (float)(kx * 2 + wo);
    float y0f = floorf(yf), x0f = floorf(xf);
    float ly = yf - y0f, lx = xf - x0f;
    int y0 = (int)y0f, x0 = (int)x0f;
    int y1 = y0 + 1,  x1 = x0 + 1;

    float w00 = (1.f - ly) * (1.f - lx);
    float w01 = (1.f - ly) * lx;
    float w10 = ly * (1.f - lx);
    float w11 = ly * lx;

    bool vy0 = (y0 >= 0) & (y0 < H_IN);
    bool vy1 = (y1 >= 0) & (y1 < H_IN);
    bool vx0 = (x0 >= 0) & (x0 < W_IN);
    bool vx1 = (x1 >= 0) & (x1 < W_IN);
    w00 *= (float)(vy0 & vx0);
    w01 *= (float)(vy0 & vx1);
    w10 *= (float)(vy1 & vx0);
    w11 *= (float)(vy1 & vx1);

    int cy0 = min(max(y0, 0), H_IN - 1);
    int cy1 = min(max(y1, 0), H_IN - 1);
    int cx0 = min(max(x0, 0), W_IN - 1);
    int cx1 = min(max(x1, 0), W_IN - 1);
    int i00 = cy0 * W_IN + cx0;
    int i01 = cy0 * W_IN + cx1;
    int i10 = cy1 * W_IN + cx0;
    int i11 = cy1 * W_IN + cx1;

    const float* xb = x + ((size_t)n * C_IN + g * CG) * (H_IN * W_IN);
    float* outb = g_col + ((size_t)n * KDIM + (size_t)(g * CG) * KKN + k) * NP + p;

    #pragma unroll 4
    for (int c = 0; c < CG; ++c) {
        const float* xc = xb + c * (H_IN * W_IN);
        float v = w00 * __ldg(xc + i00) + w01 * __ldg(xc + i01)
                + w10 * __ldg(xc + i10) + w11 * __ldg(xc + i11);
        outb[(size_t)c * (KKN * NP)] = v;
    }
}

// ---------------- launch ----------------
extern "C" void kernel_launch(void* const* d_in, const int* in_sizes, int n_in,
                              void* d_out, int out_size) {
    const float* x    = (const float*)d_in[0];   // (2,256,132,132)
    const float* offw = (const float*)d_in[1];   // (72,256,3,3)
    const float* offb = (const float*)d_in[2];   // (72,)
    const float* dw   = (const float*)d_in[3];   // (256,256,3,3)
    float* out = (float*)d_out;                  // (2,256,128,128)

    // 1) offsets = offw @ im2col(x) + bias   (im2col fused into B loads)
    {
        dim3 grid(NP / 128, 1, N_B);             // (128, 1, 2)
        sgemm128<true><<<grid, 256>>>(offw, x, nullptr, offb, M_OFF);
    }
    // 2) bilinear sampled matrix -> g_col
    {
        dim3 grid(NP / 256, GRP * KKN, N_B);     // (64, 36, 2)
        gather_sampled<<<grid, 256>>>(x);
    }
    // 3) out = dw @ sampled
    {
        dim3 grid(NP / 128, M_OUT / 128, N_B);   // (128, 2, 2)
        sgemm128<false><<<grid, 256>>>(dw, nullptr, out, nullptr, M_OUT);
    }
}

// round 4
// speedup vs baseline: 2.0457x; 1.6782x over previous
#include <cuda_runtime.h>
#include <cuda_bf16.h>
#include <cstdint>

// ---------------- problem constants ----------------
#define H_IN   132
#define W_IN   132
#define C_IN   256
#define N_B    2
#define NP     16384
#define KKN    9
#define GRP    4
#define CG     64
#define KDIM   2304
#define M_OFF  72
#define M_OUT  256
#define BK     32
#define NT     (KDIM / BK)       // 72 k-tiles

typedef unsigned long long ULL;

// ---------------- scratch (device globals) ----------------
// Sampled matrix, bf16 hi/lo planes, K-major [K][pixel], K ordered as (g*9+k)*64+c
__device__ __nv_bfloat16 g_S_hi[(size_t)N_B * KDIM * NP];
__device__ __nv_bfloat16 g_S_lo[(size_t)N_B * KDIM * NP];
// Reordered + split deform weights [m][(g*9+k)*64+c]
__device__ __nv_bfloat16 g_A_hi[(size_t)M_OUT * KDIM];
__device__ __nv_bfloat16 g_A_lo[(size_t)M_OUT * KDIM];
// offsets from GEMM1 [n][72][p]
__device__ float g_off[(size_t)N_B * M_OFF * NP];

// ---------------- helpers ----------------
__device__ __forceinline__ uint32_t smem_u32(const void* p) {
    uint32_t a;
    asm("{ .reg .u64 t; cvta.to.shared.u64 t, %1; cvt.u32.u64 %0, t; }" : "=r"(a) : "l"(p));
    return a;
}
__device__ __forceinline__ void cp16(uint32_t dst, const void* src) {
    ULL g;
    asm("cvta.to.global.u64 %0, %1;" : "=l"(g) : "l"(src));
    asm volatile("cp.async.cg.shared.global [%0], [%1], 16;" :: "r"(dst), "l"(g) : "memory");
}
#define CP_COMMIT() asm volatile("cp.async.commit_group;" ::: "memory")
#define CP_WAIT(n)  asm volatile("cp.async.wait_group %0;" :: "n"(n) : "memory")

__device__ __forceinline__ void ldsm_x4(uint32_t* r, uint32_t addr) {
    asm volatile("ldmatrix.sync.aligned.m8n8.x4.shared.b16 {%0,%1,%2,%3}, [%4];"
                 : "=r"(r[0]), "=r"(r[1]), "=r"(r[2]), "=r"(r[3]) : "r"(addr));
}
__device__ __forceinline__ void ldsm_x4t(uint32_t* r, uint32_t addr) {
    asm volatile("ldmatrix.sync.aligned.m8n8.x4.trans.shared.b16 {%0,%1,%2,%3}, [%4];"
                 : "=r"(r[0]), "=r"(r[1]), "=r"(r[2]), "=r"(r[3]) : "r"(addr));
}
__device__ __forceinline__ void mma_bf16(float* c, const uint32_t* a, const uint32_t* b) {
    asm volatile(
        "mma.sync.aligned.m16n8k16.row.col.f32.bf16.bf16.f32 "
        "{%0,%1,%2,%3}, {%4,%5,%6,%7}, {%8,%9}, {%0,%1,%2,%3};"
        : "+f"(c[0]), "+f"(c[1]), "+f"(c[2]), "+f"(c[3])
        : "r"(a[0]), "r"(a[1]), "r"(a[2]), "r"(a[3]), "r"(b[0]), "r"(b[1]));
}

// ---------------- packed-fp32 helpers (SIMT GEMM1) ----------------
__device__ __forceinline__ ULL dup2(float v) {
    ULL r; asm("mov.b64 %0, {%1, %1};" : "=l"(r) : "f"(v)); return r;
}
__device__ __forceinline__ void ffma2(ULL& d, ULL a, ULL b) {
    asm("fma.rn.f32x2 %0, %1, %2, %0;" : "+l"(d) : "l"(a), "l"(b));
}
__device__ __forceinline__ float2 u2f(ULL v) {
    float2 f; asm("mov.b64 {%0, %1}, %2;" : "=f"(f.x), "=f"(f.y) : "l"(v)); return f;
}

// ================= GEMM1 (SIMT f32x2, im2col fused): offsets =================
__global__ void __launch_bounds__(256, 2)
sgemm_off(const float* __restrict__ A, const float* __restrict__ xin,
          const float* __restrict__ bias)
{
    __shared__ float As[2][8][128];
    __shared__ float Bs[2][8][128];

    const int n   = blockIdx.z;
    const int bx  = blockIdx.x * 128;
    const int ho  = blockIdx.x;
    const int tid = threadIdx.x;
    const int ty  = tid >> 4;
    const int tx  = tid & 15;

    const int ar    = tid >> 1;
    const int acol4 = (tid & 1) * 4;
    const int brow  = tid >> 5;
    const int bcol  = (tid & 31) * 4;

    float* Cn = g_off + (size_t)n * M_OFF * NP;

    const bool aval   = (ar < M_OFF);
    const bool active = (ty * 8) < M_OFF;

    ULL acc[8][4];
    #pragma unroll
    for (int i = 0; i < 8; ++i) { acc[i][0]=0; acc[i][1]=0; acc[i][2]=0; acc[i][3]=0; }

    auto loadA = [&](int kt) -> float4 {
        if (!aval) return make_float4(0.f, 0.f, 0.f, 0.f);
        return *reinterpret_cast<const float4*>(A + (size_t)ar * KDIM + kt + acol4);
    };
    auto loadB = [&](int kt) -> float4 {
        int row = kt + brow;
        int ci  = row / 9;
        int k   = row - ci * 9;
        int ky  = k / 3;
        int kx  = k - ky * 3;
        const float* src = xin + (((size_t)n * C_IN + ci) * H_IN + (ho + 2 * ky)) * W_IN
                               + 2 * kx + bcol;
        float2 v0 = *reinterpret_cast<const float2*>(src);
        float2 v1 = *reinterpret_cast<const float2*>(src + 2);
        return make_float4(v0.x, v0.y, v1.x, v1.y);
    };
    auto stA = [&](int b, float4 v) {
        As[b][acol4 + 0][ar] = v.x; As[b][acol4 + 1][ar] = v.y;
        As[b][acol4 + 2][ar] = v.z; As[b][acol4 + 3][ar] = v.w;
    };
    auto stB = [&](int b, float4 v) {
        *reinterpret_cast<float4*>(&Bs[b][brow][bcol]) = v;
    };

    stA(0, loadA(0));
    stB(0, loadB(0));
    __syncthreads();

    int buf = 0;
    for (int kt = 8; kt <= KDIM; kt += 8) {
        float4 pa, pb;
        const bool more = (kt < KDIM);
        if (more) { pa = loadA(kt); pb = loadB(kt); }

        if (active) {
            #pragma unroll
            for (int kk = 0; kk < 8; ++kk) {
                float4 a0 = *reinterpret_cast<const float4*>(&As[buf][kk][ty * 8]);
                float4 a1 = *reinterpret_cast<const float4*>(&As[buf][kk][ty * 8 + 4]);
                const ulonglong2* bp =
                    reinterpret_cast<const ulonglong2*>(&Bs[buf][kk][tx * 8]);
                ulonglong2 q0 = bp[0];
                ulonglong2 q1 = bp[1];
                float av[8] = {a0.x, a0.y, a0.z, a0.w, a1.x, a1.y, a1.z, a1.w};
                #pragma unroll
                for (int i = 0; i < 8; ++i) {
                    ULL ad = dup2(av[i]);
                    ffma2(acc[i][0], ad, q0.x);
                    ffma2(acc[i][1], ad, q0.y);
                    ffma2(acc[i][2], ad, q1.x);
                    ffma2(acc[i][3], ad, q1.y);
                }
            }
        }

        if (more) {
            stA(buf ^ 1, pa);
            stB(buf ^ 1, pb);
            __syncthreads();
            buf ^= 1;
        }
    }

    if (!active) return;
    #pragma unroll
    for (int i = 0; i < 8; ++i) {
        int row = ty * 8 + i;
        if (row >= M_OFF) break;
        float bv = bias[row];
        float2 f0 = u2f(acc[i][0]);
        float2 f1 = u2f(acc[i][1]);
        float2 f2 = u2f(acc[i][2]);
        float2 f3 = u2f(acc[i][3]);
        float4 o0 = make_float4(f0.x + bv, f0.y + bv, f1.x + bv, f1.y + bv);
        float4 o1 = make_float4(f2.x + bv, f2.y + bv, f3.x + bv, f3.y + bv);
        float* cp = Cn + (size_t)row * NP + bx + tx * 8;
        *reinterpret_cast<float4*>(cp)     = o0;
        *reinterpret_cast<float4*>(cp + 4) = o1;
    }
}

// ================= weight prep: reorder K to (g,k,c), split hi/lo =================
__global__ void prep_w(const float* __restrict__ dw) {
    int idx = blockIdx.x * 256 + threadIdx.x;
    if (idx >= M_OUT * KDIM) return;
    int m = idx / KDIM, j = idx - m * KDIM;
    int g = j / (KKN * CG);
    int r = j - g * (KKN * CG);
    int k = r / CG;
    int c = r - k * CG;
    float v = dw[((size_t)m * C_IN + g * CG + c) * KKN + k];
    __nv_bfloat16 h = __float2bfloat16(v);
    g_A_hi[idx] = h;
    g_A_lo[idx] = __float2bfloat16(v - __bfloat162float(h));
}

// ================= gather: bilinear sample -> bf16 hi/lo planes =================
__global__ void gather_sampled(const float* __restrict__ x) {
    int n  = blockIdx.z;
    int gk = blockIdx.y;
    int g  = gk / KKN, k = gk % KKN;
    int p  = blockIdx.x * blockDim.x + threadIdx.x;
    int ho = p >> 7, wo = p & 127;
    int ky = k / 3, kx = k % 3;

    const float* offbase = g_off + ((size_t)n * M_OFF + g * 18 + k * 2) * NP + p;
    float dy = offbase[0];
    float dx = offbase[NP];

    float yf = dy + (float)(ky * 2 + ho);
    float xf = dx + (float)(kx * 2 + wo);
    float y0f = floorf(yf), x0f = floorf(xf);
    float ly = yf - y0f, lx = xf - x0f;
    int y0 = (int)y0f, x0 = (int)x0f;
    int y1 = y0 + 1,  x1 = x0 + 1;

    float w00 = (1.f - ly) * (1.f - lx);
    float w01 = (1.f - ly) * lx;
    float w10 = ly * (1.f - lx);
    float w11 = ly * lx;

    bool vy0 = (y0 >= 0) & (y0 < H_IN);
    bool vy1 = (y1 >= 0) & (y1 < H_IN);
    bool vx0 = (x0 >= 0) & (x0 < W_IN);
    bool vx1 = (x1 >= 0) & (x1 < W_IN);
    w00 *= (float)(vy0 & vx0);
    w01 *= (float)(vy0 & vx1);
    w10 *= (float)(vy1 & vx0);
    w11 *= (float)(vy1 & vx1);

    int cy0 = min(max(y0, 0), H_IN - 1);
    int cy1 = min(max(y1, 0), H_IN - 1);
    int cx0 = min(max(x0, 0), W_IN - 1);
    int cx1 = min(max(x1, 0), W_IN - 1);
    int i00 = cy0 * W_IN + cx0;
    int i01 = cy0 * W_IN + cx1;
    int i10 = cy1 * W_IN + cx0;
    int i11 = cy1 * W_IN + cx1;

    const float* xb = x + ((size_t)n * C_IN + g * CG) * (H_IN * W_IN);
    size_t base = ((size_t)n * KDIM + (size_t)(g * KKN + k) * CG) * NP + p;
    __nv_bfloat16* hib = g_S_hi + base;
    __nv_bfloat16* lob = g_S_lo + base;

    #pragma unroll 4
    for (int c = 0; c < CG; ++c) {
        const float* xc = xb + c * (H_IN * W_IN);
        float v = w00 * __ldg(xc + i00) + w01 * __ldg(xc + i01)
                + w10 * __ldg(xc + i10) + w11 * __ldg(xc + i11);
        __nv_bfloat16 h = __float2bfloat16(v);
        hib[(size_t)c * NP] = h;
        lob[(size_t)c * NP] = __float2bfloat16(v - __bfloat162float(h));
    }
}

// ================= GEMM2: HMMA m16n8k16 bf16, 3-term split =================
// Block tile 128m x 128n x BK32. 8 warps (2m x 4n), warp tile 64m x 32n.
// smem pitches: A 80B/row (32 bf16 + pad), B 272B/row (128 bf16 + pad).
#define A_PITCH 80
#define B_PITCH 272
#define SA_PLANE (128 * A_PITCH)         // 10240
#define SB_PLANE (32 * B_PITCH)          // 8704
#define OFF_AH 0
#define OFF_AL SA_PLANE
#define OFF_BH (2 * SA_PLANE)
#define OFF_BL (2 * SA_PLANE + SB_PLANE)
#define BUF_BYTES (2 * SA_PLANE + 2 * SB_PLANE)   // 37888
#define SMEM2_BYTES (2 * BUF_BYTES)               // 75776

__global__ void __launch_bounds__(256, 2)
gemm2_mma(float* __restrict__ out)
{
    extern __shared__ char smem[];
    const uint32_t sb = smem_u32(smem);

    const int tid = threadIdx.x;
    const int wid = tid >> 5;
    const int l   = tid & 31;

    const int my = blockIdx.x;       // 0..1 M tile (fastest -> B reuse in L2)
    const int bx = blockIdx.y;       // 0..127 pixel tile
    const int n  = blockIdx.z;

    const int wm = (wid & 1) * 64;   // warp m base in tile
    const int wn = (wid >> 1) * 32;  // warp n base in tile

    const __nv_bfloat16* Ah = g_A_hi + (size_t)my * 128 * KDIM;
    const __nv_bfloat16* Al = g_A_lo + (size_t)my * 128 * KDIM;
    const __nv_bfloat16* Sh = g_S_hi + (size_t)n * KDIM * NP + (size_t)bx * 128;
    const __nv_bfloat16* Sl = g_S_lo + (size_t)n * KDIM * NP + (size_t)bx * 128;

    // ldmatrix lane-derived address components
    const int a_row = ((l >> 3) & 1) * 8 + (l & 7);   // row within m16 tile
    const int a_kb  = (l >> 4) * 8;                    // k sub-block
    const int b_kr  = ((l >> 3) & 1) * 8 + (l & 7);   // k row
    const int b_nb  = (l >> 4) * 8;                    // n sub-block

    float acc[4][4][4];
    #pragma unroll
    for (int i = 0; i < 4; ++i)
        #pragma unroll
        for (int j = 0; j < 4; ++j)
            #pragma unroll
            for (int q = 0; q < 4; ++q) acc[i][j][q] = 0.f;

    auto load_tile = [&](int kt, int b) {
        uint32_t base = sb + b * BUF_BYTES;
        // A planes: 512 chunks each (128 rows x 4 x 16B)
        #pragma unroll
        for (int i = 0; i < 2; ++i) {
            int c = tid + i * 256;
            int r = c >> 2, j = c & 3;
            uint32_t dst = base + r * A_PITCH + j * 16;
            cp16(dst + OFF_AH, Ah + (size_t)r * KDIM + kt + j * 8);
            cp16(dst + OFF_AL, Al + (size_t)r * KDIM + kt + j * 8);
        }
        // B planes: 512 chunks each (32 rows x 16 x 16B)
        #pragma unroll
        for (int i = 0; i < 2; ++i) {
            int c = tid + i * 256;
            int r = c >> 4, j = c & 15;
            uint32_t dst = base + r * B_PITCH + j * 16;
            cp16(dst + OFF_BH, Sh + (size_t)(kt + r) * NP + j * 8);
            cp16(dst + OFF_BL, Sl + (size_t)(kt + r) * NP + j * 8);
        }
        CP_COMMIT();
    };

    load_tile(0, 0);

    for (int t = 0; t < NT; ++t) {
        int b = t & 1;
        if (t + 1 < NT) {
            load_tile((t + 1) * BK, b ^ 1);
            CP_WAIT(1);
        } else {
            CP_WAIT(0);
        }
        __syncthreads();

        uint32_t base = sb + b * BUF_BYTES;
        #pragma unroll
        for (int k16 = 0; k16 < BK; k16 += 16) {
            #pragma unroll
            for (int pass = 0; pass < 3; ++pass) {
                uint32_t abase = base + ((pass == 2) ? OFF_AL : OFF_AH);
                uint32_t bbase = base + ((pass == 1) ? OFF_BL : OFF_BH);
                uint32_t afr[4][4];
                #pragma unroll
                for (int mt = 0; mt < 4; ++mt)
                    ldsm_x4(afr[mt],
                            abase + (wm + mt * 16 + a_row) * A_PITCH + (k16 + a_kb) * 2);
                uint32_t bfr[4][2];
                #pragma unroll
                for (int nt2 = 0; nt2 < 2; ++nt2) {
                    uint32_t r[4];
                    ldsm_x4t(r, bbase + (k16 + b_kr) * B_PITCH + (wn + nt2 * 16 + b_nb) * 2);
                    bfr[nt2 * 2][0]     = r[0];
                    bfr[nt2 * 2][1]     = r[1];
                    bfr[nt2 * 2 + 1][0] = r[2];
                    bfr[nt2 * 2 + 1][1] = r[3];
                }
                #pragma unroll
                for (int mt = 0; mt < 4; ++mt)
                    #pragma unroll
                    for (int nt = 0; nt < 4; ++nt)
                        mma_bf16(acc[mt][nt], afr[mt], bfr[nt]);
            }
        }
        __syncthreads();
    }

    // epilogue
    float* ob = out + ((size_t)n * M_OUT + my * 128 + wm) * NP + (size_t)bx * 128 + wn;
    #pragma unroll
    for (int mt = 0; mt < 4; ++mt) {
        #pragma unroll
        for (int nt = 0; nt < 4; ++nt) {
            int row = mt * 16 + (l >> 2);
            int col = nt * 8 + (l & 3) * 2;
            float* p0 = ob + (size_t)row * NP + col;
            *reinterpret_cast<float2*>(p0) =
                make_float2(acc[mt][nt][0], acc[mt][nt][1]);
            *reinterpret_cast<float2*>(p0 + 8 * NP) =
                make_float2(acc[mt][nt][2], acc[mt][nt][3]);
        }
    }
}

// ---------------- launch ----------------
extern "C" void kernel_launch(void* const* d_in, const int* in_sizes, int n_in,
                              void* d_out, int out_size) {
    const float* x    = (const float*)d_in[0];   // (2,256,132,132)
    const float* offw = (const float*)d_in[1];   // (72,256,3,3)
    const float* offb = (const float*)d_in[2];   // (72,)
    const float* dw   = (const float*)d_in[3];   // (256,256,3,3)
    float* out = (float*)d_out;                  // (2,256,128,128)

    cudaFuncSetAttribute(gemm2_mma, cudaFuncAttributeMaxDynamicSharedMemorySize,
                         SMEM2_BYTES);

    // 0) weight reorder/split
    prep_w<<<(M_OUT * KDIM + 255) / 256, 256>>>(dw);
    // 1) offsets = offw @ im2col(x) + bias (SIMT f32x2, fused im2col)
    {
        dim3 grid(NP / 128, 1, N_B);
        sgemm_off<<<grid, 256>>>(offw, x, offb);
    }
    // 2) bilinear sampled matrix -> bf16 hi/lo planes
    {
        dim3 grid(NP / 256, GRP * KKN, N_B);
        gather_sampled<<<grid, 256>>>(x);
    }
    // 3) out = dw @ sampled  (HMMA bf16, 3-term split)
    {
        dim3 grid(2, NP / 128, N_B);
        gemm2_mma<<<grid, 256, SMEM2_BYTES>>>(out);
    }
}

// round 5
// speedup vs baseline: 2.5024x; 1.2232x over previous
#include <cuda_runtime.h>
#include <cuda_bf16.h>
#include <cstdint>

// ---------------- problem constants ----------------
#define H_IN   132
#define W_IN   132
#define C_IN   256
#define N_B    2
#define NP     16384
#define KKN    9
#define GRP    4
#define CG     64
#define KDIM   2304
#define M_OFF  72
#define M_PAD  80
#define M_OUT  256
#define BK     32
#define NT     (KDIM / BK)       // 72 k-tiles

typedef unsigned long long ULL;

// ---------------- scratch (device globals) ----------------
__device__ __nv_bfloat16 g_S_hi[(size_t)N_B * KDIM * NP];
__device__ __nv_bfloat16 g_S_lo[(size_t)N_B * KDIM * NP];
__device__ __nv_bfloat16 g_A_hi[(size_t)M_OUT * KDIM];   // deform weights (g,k,c) order
__device__ __nv_bfloat16 g_A_lo[(size_t)M_OUT * KDIM];
__device__ __nv_bfloat16 g_A1_hi[(size_t)M_PAD * KDIM];  // offset weights, padded to 80 rows
__device__ __nv_bfloat16 g_A1_lo[(size_t)M_PAD * KDIM];
__device__ float g_off[(size_t)N_B * M_OFF * NP];

// ---------------- helpers ----------------
__device__ __forceinline__ uint32_t smem_u32(const void* p) {
    uint32_t a;
    asm("{ .reg .u64 t; cvta.to.shared.u64 t, %1; cvt.u32.u64 %0, t; }" : "=r"(a) : "l"(p));
    return a;
}
__device__ __forceinline__ void cp16(uint32_t dst, const void* src) {
    ULL g;
    asm("cvta.to.global.u64 %0, %1;" : "=l"(g) : "l"(src));
    asm volatile("cp.async.cg.shared.global [%0], [%1], 16;" :: "r"(dst), "l"(g) : "memory");
}
#define CP_COMMIT() asm volatile("cp.async.commit_group;" ::: "memory")
#define CP_WAIT(n)  asm volatile("cp.async.wait_group %0;" :: "n"(n) : "memory")

__device__ __forceinline__ void ldsm_x4(uint32_t* r, uint32_t addr) {
    asm volatile("ldmatrix.sync.aligned.m8n8.x4.shared.b16 {%0,%1,%2,%3}, [%4];"
                 : "=r"(r[0]), "=r"(r[1]), "=r"(r[2]), "=r"(r[3]) : "r"(addr));
}
__device__ __forceinline__ void ldsm_x4t(uint32_t* r, uint32_t addr) {
    asm volatile("ldmatrix.sync.aligned.m8n8.x4.trans.shared.b16 {%0,%1,%2,%3}, [%4];"
                 : "=r"(r[0]), "=r"(r[1]), "=r"(r[2]), "=r"(r[3]) : "r"(addr));
}
__device__ __forceinline__ void mma_bf16(float* c, const uint32_t* a, const uint32_t* b) {
    asm volatile(
        "mma.sync.aligned.m16n8k16.row.col.f32.bf16.bf16.f32 "
        "{%0,%1,%2,%3}, {%4,%5,%6,%7}, {%8,%9}, {%0,%1,%2,%3};"
        : "+f"(c[0]), "+f"(c[1]), "+f"(c[2]), "+f"(c[3])
        : "r"(a[0]), "r"(a[1]), "r"(a[2]), "r"(a[3]), "r"(b[0]), "r"(b[1]));
}
__device__ __forceinline__ uint32_t pack2bf(float a, float b) {
    __nv_bfloat162 h = __floats2bfloat162_rn(a, b);
    return *reinterpret_cast<uint32_t*>(&h);
}

// ================= weight prep =================
__global__ void prep_w(const float* __restrict__ dw) {
    int idx = blockIdx.x * 256 + threadIdx.x;
    if (idx >= M_OUT * KDIM) return;
    int m = idx / KDIM, j = idx - m * KDIM;
    int g = j / (KKN * CG);
    int r = j - g * (KKN * CG);
    int k = r / CG;
    int c = r - k * CG;
    float v = dw[((size_t)m * C_IN + g * CG + c) * KKN + k];
    __nv_bfloat16 h = __float2bfloat16(v);
    g_A_hi[idx] = h;
    g_A_lo[idx] = __float2bfloat16(v - __bfloat162float(h));
}
__global__ void prep_w1(const float* __restrict__ offw) {
    int idx = blockIdx.x * 256 + threadIdx.x;
    if (idx >= M_PAD * KDIM) return;
    int m = idx / KDIM, j = idx - m * KDIM;
    float v = (m < M_OFF) ? offw[(size_t)m * KDIM + j] : 0.f;   // im2col order ci*9+k
    __nv_bfloat16 h = __float2bfloat16(v);
    g_A1_hi[idx] = h;
    g_A1_lo[idx] = __float2bfloat16(v - __bfloat162float(h));
}

// ================= GEMM1: offsets via HMMA (im2col + bf16 split fused) =================
// Block: 80m x 256n x 32k. 8 warps, warp = 80m x 32n. Grid (64, 1, 2).
#define A1_PITCH 80
#define B1_PITCH 528
#define SA1 (M_PAD * A1_PITCH)           // 6400
#define SB1 (BK * B1_PITCH)              // 16896
#define OFF_A1H 0
#define OFF_A1L SA1
#define OFF_B1H (2 * SA1)
#define OFF_B1L (2 * SA1 + SB1)
#define BUF1 (2 * SA1 + 2 * SB1)         // 46592
#define SMEM1 (2 * BUF1)                 // 93184

__global__ void __launch_bounds__(256, 1)
gemm1_mma(const float* __restrict__ xin, const float* __restrict__ bias)
{
    extern __shared__ char smem[];
    const uint32_t sb = smem_u32(smem);

    const int tid = threadIdx.x;
    const int wid = tid >> 5;
    const int l   = tid & 31;
    const int n   = blockIdx.z;
    const int p0  = blockIdx.x * 256;     // pixel tile base
    const int ho0 = p0 >> 7;              // first output row of tile

    const int wn = wid * 32;              // warp n base

    // B load mapping: r = k-row (0..31), seg = 0..7 -> 32-pixel segment
    const int br   = tid >> 3;
    const int seg  = tid & 7;
    const int hseg = seg >> 2;            // 0/1: which output row
    const int wo0  = (seg & 3) * 32;      // wo base of segment

    // ldmatrix lane addressing
    const int a_row = ((l >> 3) & 1) * 8 + (l & 7);
    const int a_kb  = (l >> 4) * 8;
    const int b_kr  = ((l >> 3) & 1) * 8 + (l & 7);
    const int b_nb  = (l >> 4) * 8;

    float acc[5][4][4];
    #pragma unroll
    for (int i = 0; i < 5; ++i)
        #pragma unroll
        for (int j = 0; j < 4; ++j)
            #pragma unroll
            for (int q = 0; q < 4; ++q) acc[i][j][q] = 0.f;

    auto cpA = [&](int kt, int b) {
        uint32_t base = sb + b * BUF1;
        #pragma unroll
        for (int i = 0; i < 2; ++i) {
            int c = tid + i * 256;
            if (c < 320) {
                int r = c >> 2, j = c & 3;
                uint32_t dst = base + r * A1_PITCH + j * 16;
                cp16(dst + OFF_A1H, g_A1_hi + (size_t)r * KDIM + kt + j * 8);
                cp16(dst + OFF_A1L, g_A1_lo + (size_t)r * KDIM + kt + j * 8);
            }
        }
        CP_COMMIT();
    };

    uint32_t hi[16], lo[16];
    auto ldB = [&](int kt) {
        int j  = kt + br;
        int ci = j / 9;
        int kk = j - ci * 9;
        int ky = kk / 3;
        int kx = kk - ky * 3;
        const float* src = xin + (((size_t)n * C_IN + ci) * H_IN + (ho0 + hseg + 2 * ky)) * W_IN
                               + wo0 + 2 * kx;
        #pragma unroll
        for (int i = 0; i < 16; ++i) {
            float2 v = *reinterpret_cast<const float2*>(src + 2 * i);
            float h0f, h1f;
            {
                __nv_bfloat16 h0 = __float2bfloat16(v.x);
                __nv_bfloat16 h1 = __float2bfloat16(v.y);
                h0f = __bfloat162float(h0);
                h1f = __bfloat162float(h1);
                __nv_bfloat162 hp; hp.x = h0; hp.y = h1;
                hi[i] = *reinterpret_cast<uint32_t*>(&hp);
            }
            lo[i] = pack2bf(v.x - h0f, v.y - h1f);
        }
    };
    auto stB = [&](int b) {
        uint32_t base = sb + b * BUF1 + br * B1_PITCH + (hseg * 128 + wo0) * 2;
        #pragma unroll
        for (int i = 0; i < 16; ++i) {
            *reinterpret_cast<uint32_t*>(smem + (base - sb) + OFF_B1H + i * 4) = hi[i];
            *reinterpret_cast<uint32_t*>(smem + (base - sb) + OFF_B1L + i * 4) = lo[i];
        }
    };

    // prologue
    cpA(0, 0);
    ldB(0);
    stB(0);
    CP_WAIT(0);
    __syncthreads();

    int buf = 0;
    for (int t = 0; t < NT; ++t) {
        const bool more = (t + 1 < NT);
        if (more) {
            cpA((t + 1) * BK, buf ^ 1);
            ldB((t + 1) * BK);
        }

        uint32_t base = sb + buf * BUF1;
        #pragma unroll
        for (int k16 = 0; k16 < BK; k16 += 16) {
            #pragma unroll
            for (int pass = 0; pass < 3; ++pass) {
                uint32_t abase = base + ((pass == 2) ? OFF_A1L : OFF_A1H);
                uint32_t bbase = base + ((pass == 1) ? OFF_B1L : OFF_B1H);
                uint32_t af[5][4];
                #pragma unroll
                for (int mt = 0; mt < 5; ++mt)
                    ldsm_x4(af[mt], abase + (mt * 16 + a_row) * A1_PITCH + (k16 + a_kb) * 2);
                uint32_t bfr[4][2];
                #pragma unroll
                for (int nt2 = 0; nt2 < 2; ++nt2) {
                    uint32_t r[4];
                    ldsm_x4t(r, bbase + (k16 + b_kr) * B1_PITCH + (wn + nt2 * 16 + b_nb) * 2);
                    bfr[nt2 * 2][0]     = r[0];
                    bfr[nt2 * 2][1]     = r[1];
                    bfr[nt2 * 2 + 1][0] = r[2];
                    bfr[nt2 * 2 + 1][1] = r[3];
                }
                #pragma unroll
                for (int mt = 0; mt < 5; ++mt)
                    #pragma unroll
                    for (int nt = 0; nt < 4; ++nt)
                        mma_bf16(acc[mt][nt], af[mt], bfr[nt]);
            }
        }

        if (more) {
            __syncthreads();          // everyone done reading buf^1's previous contents
            stB(buf ^ 1);
            CP_WAIT(0);
            __syncthreads();
            buf ^= 1;
        }
    }

    // epilogue: rows 0..71, add bias
    float* ob = g_off + (size_t)n * M_OFF * NP + p0 + wn;
    #pragma unroll
    for (int mt = 0; mt < 5; ++mt) {
        int row = mt * 16 + (l >> 2);
        float bv0 = bias[row];
        #pragma unroll
        for (int nt = 0; nt < 4; ++nt) {
            int col = nt * 8 + (l & 3) * 2;
            float* p = ob + (size_t)row * NP + col;
            *reinterpret_cast<float2*>(p) =
                make_float2(acc[mt][nt][0] + bv0, acc[mt][nt][1] + bv0);
        }
        if (mt < 4) {
            float bv1 = bias[row + 8];
            #pragma unroll
            for (int nt = 0; nt < 4; ++nt) {
                int col = nt * 8 + (l & 3) * 2;
                float* p = ob + (size_t)(row + 8) * NP + col;
                *reinterpret_cast<float2*>(p) =
                    make_float2(acc[mt][nt][2] + bv1, acc[mt][nt][3] + bv1);
            }
        }
    }
}

// ================= gather: bilinear sample -> bf16 hi/lo planes =================
__global__ void gather_sampled(const float* __restrict__ x) {
    int n  = blockIdx.z;
    int gk = blockIdx.y;
    int g  = gk / KKN, k = gk % KKN;
    int p  = blockIdx.x * blockDim.x + threadIdx.x;
    int ho = p >> 7, wo = p & 127;
    int ky = k / 3, kx = k % 3;

    const float* offbase = g_off + ((size_t)n * M_OFF + g * 18 + k * 2) * NP + p;
    float dy = offbase[0];
    float dx = offbase[NP];

    float yf = dy + (float)(ky * 2 + ho);
    float xf = dx + (float)(kx * 2 + wo);
    float y0f = floorf(yf), x0f = floorf(xf);
    float ly = yf - y0f, lx = xf - x0f;
    int y0 = (int)y0f, x0 = (int)x0f;
    int y1 = y0 + 1,  x1 = x0 + 1;

    float w00 = (1.f - ly) * (1.f - lx);
    float w01 = (1.f - ly) * lx;
    float w10 = ly * (1.f - lx);
    float w11 = ly * lx;

    bool vy0 = (y0 >= 0) & (y0 < H_IN);
    bool vy1 = (y1 >= 0) & (y1 < H_IN);
    bool vx0 = (x0 >= 0) & (x0 < W_IN);
    bool vx1 = (x1 >= 0) & (x1 < W_IN);
    w00 *= (float)(vy0 & vx0);
    w01 *= (float)(vy0 & vx1);
    w10 *= (float)(vy1 & vx0);
    w11 *= (float)(vy1 & vx1);

    int cy0 = min(max(y0, 0), H_IN - 1);
    int cy1 = min(max(y1, 0), H_IN - 1);
    int cx0 = min(max(x0, 0), W_IN - 1);
    int cx1 = min(max(x1, 0), W_IN - 1);
    int i00 = cy0 * W_IN + cx0;
    int i01 = cy0 * W_IN + cx1;
    int i10 = cy1 * W_IN + cx0;
    int i11 = cy1 * W_IN + cx1;

    const float* xb = x + ((size_t)n * C_IN + g * CG) * (H_IN * W_IN);
    size_t base = ((size_t)n * KDIM + (size_t)(g * KKN + k) * CG) * NP + p;
    __nv_bfloat16* hib = g_S_hi + base;
    __nv_bfloat16* lob = g_S_lo + base;

    #pragma unroll 4
    for (int c = 0; c < CG; ++c) {
        const float* xc = xb + c * (H_IN * W_IN);
        float v = w00 * __ldg(xc + i00) + w01 * __ldg(xc + i01)
                + w10 * __ldg(xc + i10) + w11 * __ldg(xc + i11);
        __nv_bfloat16 h = __float2bfloat16(v);
        hib[(size_t)c * NP] = h;
        lob[(size_t)c * NP] = __float2bfloat16(v - __bfloat162float(h));
    }
}

// ================= GEMM2: HMMA m16n8k16 bf16, 3-term split =================
#define A_PITCH 80
#define B_PITCH 272
#define SA_PLANE (128 * A_PITCH)
#define SB_PLANE (32 * B_PITCH)
#define OFF_AH 0
#define OFF_AL SA_PLANE
#define OFF_BH (2 * SA_PLANE)
#define OFF_BL (2 * SA_PLANE + SB_PLANE)
#define BUF_BYTES (2 * SA_PLANE + 2 * SB_PLANE)
#define SMEM2_BYTES (2 * BUF_BYTES)

__global__ void __launch_bounds__(256, 2)
gemm2_mma(float* __restrict__ out)
{
    extern __shared__ char smem[];
    const uint32_t sb = smem_u32(smem);

    const int tid = threadIdx.x;
    const int wid = tid >> 5;
    const int l   = tid & 31;

    const int my = blockIdx.x;
    const int bx = blockIdx.y;
    const int n  = blockIdx.z;

    const int wm = (wid & 1) * 64;
    const int wn = (wid >> 1) * 32;

    const __nv_bfloat16* Ah = g_A_hi + (size_t)my * 128 * KDIM;
    const __nv_bfloat16* Al = g_A_lo + (size_t)my * 128 * KDIM;
    const __nv_bfloat16* Sh = g_S_hi + (size_t)n * KDIM * NP + (size_t)bx * 128;
    const __nv_bfloat16* Sl = g_S_lo + (size_t)n * KDIM * NP + (size_t)bx * 128;

    const int a_row = ((l >> 3) & 1) * 8 + (l & 7);
    const int a_kb  = (l >> 4) * 8;
    const int b_kr  = ((l >> 3) & 1) * 8 + (l & 7);
    const int b_nb  = (l >> 4) * 8;

    float acc[4][4][4];
    #pragma unroll
    for (int i = 0; i < 4; ++i)
        #pragma unroll
        for (int j = 0; j < 4; ++j)
            #pragma unroll
            for (int q = 0; q < 4; ++q) acc[i][j][q] = 0.f;

    auto load_tile = [&](int kt, int b) {
        uint32_t base = sb + b * BUF_BYTES;
        #pragma unroll
        for (int i = 0; i < 2; ++i) {
            int c = tid + i * 256;
            int r = c >> 2, j = c & 3;
            uint32_t dst = base + r * A_PITCH + j * 16;
            cp16(dst + OFF_AH, Ah + (size_t)r * KDIM + kt + j * 8);
            cp16(dst + OFF_AL, Al + (size_t)r * KDIM + kt + j * 8);
        }
        #pragma unroll
        for (int i = 0; i < 2; ++i) {
            int c = tid + i * 256;
            int r = c >> 4, j = c & 15;
            uint32_t dst = base + r * B_PITCH + j * 16;
            cp16(dst + OFF_BH, Sh + (size_t)(kt + r) * NP + j * 8);
            cp16(dst + OFF_BL, Sl + (size_t)(kt + r) * NP + j * 8);
        }
        CP_COMMIT();
    };

    load_tile(0, 0);

    for (int t = 0; t < NT; ++t) {
        int b = t & 1;
        if (t + 1 < NT) {
            load_tile((t + 1) * BK, b ^ 1);
            CP_WAIT(1);
        } else {
            CP_WAIT(0);
        }
        __syncthreads();

        uint32_t base = sb + b * BUF_BYTES;
        #pragma unroll
        for (int k16 = 0; k16 < BK; k16 += 16) {
            #pragma unroll
            for (int pass = 0; pass < 3; ++pass) {
                uint32_t abase = base + ((pass == 2) ? OFF_AL : OFF_AH);
                uint32_t bbase = base + ((pass == 1) ? OFF_BL : OFF_BH);
                uint32_t afr[4][4];
                #pragma unroll
                for (int mt = 0; mt < 4; ++mt)
                    ldsm_x4(afr[mt],
                            abase + (wm + mt * 16 + a_row) * A_PITCH + (k16 + a_kb) * 2);
                uint32_t bfr[4][2];
                #pragma unroll
                for (int nt2 = 0; nt2 < 2; ++nt2) {
                    uint32_t r[4];
                    ldsm_x4t(r, bbase + (k16 + b_kr) * B_PITCH + (wn + nt2 * 16 + b_nb) * 2);
                    bfr[nt2 * 2][0]     = r[0];
                    bfr[nt2 * 2][1]     = r[1];
                    bfr[nt2 * 2 + 1][0] = r[2];
                    bfr[nt2 * 2 + 1][1] = r[3];
                }
                #pragma unroll
                for (int mt = 0; mt < 4; ++mt)
                    #pragma unroll
                    for (int nt = 0; nt < 4; ++nt)
                        mma_bf16(acc[mt][nt], afr[mt], bfr[nt]);
            }
        }
        __syncthreads();
    }

    float* ob = out + ((size_t)n * M_OUT + my * 128 + wm) * NP + (size_t)bx * 128 + wn;
    #pragma unroll
    for (int mt = 0; mt < 4; ++mt) {
        #pragma unroll
        for (int nt = 0; nt < 4; ++nt) {
            int row = mt * 16 + (l >> 2);
            int col = nt * 8 + (l & 3) * 2;
            float* p0 = ob + (size_t)row * NP + col;
            *reinterpret_cast<float2*>(p0) =
                make_float2(acc[mt][nt][0], acc[mt][nt][1]);
            *reinterpret_cast<float2*>(p0 + 8 * NP) =
                make_float2(acc[mt][nt][2], acc[mt][nt][3]);
        }
    }
}

// ---------------- launch ----------------
extern "C" void kernel_launch(void* const* d_in, const int* in_sizes, int n_in,
                              void* d_out, int out_size) {
    const float* x    = (const float*)d_in[0];
    const float* offw = (const float*)d_in[1];
    const float* offb = (const float*)d_in[2];
    const float* dw   = (const float*)d_in[3];
    float* out = (float*)d_out;

    cudaFuncSetAttribute(gemm1_mma, cudaFuncAttributeMaxDynamicSharedMemorySize, SMEM1);
    cudaFuncSetAttribute(gemm2_mma, cudaFuncAttributeMaxDynamicSharedMemorySize, SMEM2_BYTES);

    prep_w <<<(M_OUT * KDIM + 255) / 256, 256>>>(dw);
    prep_w1<<<(M_PAD * KDIM + 255) / 256, 256>>>(offw);
    // 1) offsets via tensor cores (im2col + bf16 split fused)
    {
        dim3 grid(NP / 256, 1, N_B);
        gemm1_mma<<<grid, 256, SMEM1>>>(x, offb);
    }
    // 2) bilinear sampled matrix -> bf16 hi/lo planes
    {
        dim3 grid(NP / 256, GRP * KKN, N_B);
        gather_sampled<<<grid, 256>>>(x);
    }
    // 3) out = dw @ sampled
    {
        dim3 grid(2, NP / 128, N_B);
        gemm2_mma<<<grid, 256, SMEM2_BYTES>>>(out);
    }
}

// round 6
// speedup vs baseline: 2.7112x; 1.0834x over previous
#include <cuda_runtime.h>
#include <cuda_bf16.h>
#include <cstdint>

// ---------------- problem constants ----------------
#define H_IN   132
#define W_IN   132
#define C_IN   256
#define N_B    2
#define NP     16384
#define KKN    9
#define GRP    4
#define CG     64
#define KDIM   2304
#define M_OFF  72
#define M_PAD  80
#define M_OUT  256
#define BK     32
#define NT     (KDIM / BK)       // 72 k-tiles

typedef unsigned long long ULL;

// ---------------- scratch (device globals) ----------------
__device__ __nv_bfloat16 g_S_hi[(size_t)N_B * KDIM * NP];
__device__ __nv_bfloat16 g_S_lo[(size_t)N_B * KDIM * NP];
__device__ __nv_bfloat16 g_A_hi[(size_t)M_OUT * KDIM];   // deform weights (g,k,c) order
__device__ __nv_bfloat16 g_A_lo[(size_t)M_OUT * KDIM];
__device__ __nv_bfloat16 g_A1_hi[(size_t)M_PAD * KDIM];  // offset weights, padded
__device__ __nv_bfloat16 g_A1_lo[(size_t)M_PAD * KDIM];
// x split to bf16 hi/lo, 3 kx-shifted copies: [kx][n][ci][y][wo0..127]
#define XPLANE ((size_t)N_B * C_IN * H_IN * 128)
__device__ __nv_bfloat16 g_X_hi[3 * XPLANE];
__device__ __nv_bfloat16 g_X_lo[3 * XPLANE];
__device__ float g_off[(size_t)N_B * M_OFF * NP];

// ---------------- helpers ----------------
__device__ __forceinline__ uint32_t smem_u32(const void* p) {
    uint32_t a;
    asm("{ .reg .u64 t; cvta.to.shared.u64 t, %1; cvt.u32.u64 %0, t; }" : "=r"(a) : "l"(p));
    return a;
}
__device__ __forceinline__ void cp16(uint32_t dst, const void* src) {
    ULL g;
    asm("cvta.to.global.u64 %0, %1;" : "=l"(g) : "l"(src));
    asm volatile("cp.async.cg.shared.global [%0], [%1], 16;" :: "r"(dst), "l"(g) : "memory");
}
#define CP_COMMIT() asm volatile("cp.async.commit_group;" ::: "memory")
#define CP_WAIT(n)  asm volatile("cp.async.wait_group %0;" :: "n"(n) : "memory")

__device__ __forceinline__ void ldsm_x4(uint32_t* r, uint32_t addr) {
    asm volatile("ldmatrix.sync.aligned.m8n8.x4.shared.b16 {%0,%1,%2,%3}, [%4];"
                 : "=r"(r[0]), "=r"(r[1]), "=r"(r[2]), "=r"(r[3]) : "r"(addr));
}
__device__ __forceinline__ void ldsm_x4t(uint32_t* r, uint32_t addr) {
    asm volatile("ldmatrix.sync.aligned.m8n8.x4.trans.shared.b16 {%0,%1,%2,%3}, [%4];"
                 : "=r"(r[0]), "=r"(r[1]), "=r"(r[2]), "=r"(r[3]) : "r"(addr));
}
__device__ __forceinline__ void mma_bf16(float* c, const uint32_t* a, const uint32_t* b) {
    asm volatile(
        "mma.sync.aligned.m16n8k16.row.col.f32.bf16.bf16.f32 "
        "{%0,%1,%2,%3}, {%4,%5,%6,%7}, {%8,%9}, {%0,%1,%2,%3};"
        : "+f"(c[0]), "+f"(c[1]), "+f"(c[2]), "+f"(c[3])
        : "r"(a[0]), "r"(a[1]), "r"(a[2]), "r"(a[3]), "r"(b[0]), "r"(b[1]));
}

// ================= prep kernels =================
__global__ void prep_w(const float* __restrict__ dw) {
    int idx = blockIdx.x * 256 + threadIdx.x;
    if (idx >= M_OUT * KDIM) return;
    int m = idx / KDIM, j = idx - m * KDIM;
    int g = j / (KKN * CG);
    int r = j - g * (KKN * CG);
    int k = r / CG;
    int c = r - k * CG;
    float v = dw[((size_t)m * C_IN + g * CG + c) * KKN + k];
    __nv_bfloat16 h = __float2bfloat16(v);
    g_A_hi[idx] = h;
    g_A_lo[idx] = __float2bfloat16(v - __bfloat162float(h));
}
__global__ void prep_w1(const float* __restrict__ offw) {
    int idx = blockIdx.x * 256 + threadIdx.x;
    if (idx >= M_PAD * KDIM) return;
    int m = idx / KDIM, j = idx - m * KDIM;
    float v = (m < M_OFF) ? offw[(size_t)m * KDIM + j] : 0.f;
    __nv_bfloat16 h = __float2bfloat16(v);
    g_A1_hi[idx] = h;
    g_A1_lo[idx] = __float2bfloat16(v - __bfloat162float(h));
}
// split x -> bf16 hi/lo, 3 kx-shifted copies (wo window 0..127 + 2kx)
__global__ void prep_x(const float* __restrict__ x) {
    size_t idx = (size_t)blockIdx.x * 256 + threadIdx.x;
    if (idx >= XPLANE) return;
    int wo = (int)(idx & 127);
    size_t rest = idx >> 7;           // (n*C + ci)*132 + y
    int y = (int)(rest % H_IN);
    size_t nc = rest / H_IN;
    const float* row = x + (nc * H_IN + y) * W_IN;
    #pragma unroll
    for (int kx = 0; kx < 3; ++kx) {
        float v = row[wo + 2 * kx];
        __nv_bfloat16 h = __float2bfloat16(v);
        g_X_hi[kx * XPLANE + idx] = h;
        g_X_lo[kx * XPLANE + idx] = __float2bfloat16(v - __bfloat162float(h));
    }
}

// ================= GEMM1: offsets via HMMA, pure cp.async im2col =================
// Block 80m x 256n x 32k, 8 warps (warp = 80m x 32n). Grid (64, 1, 2).
#define A1_PITCH 80
#define B1_PITCH 528
#define SA1 (M_PAD * A1_PITCH)           // 6400
#define SB1 (BK * B1_PITCH)              // 16896
#define OFF_A1H 0
#define OFF_A1L SA1
#define OFF_B1H (2 * SA1)
#define OFF_B1L (2 * SA1 + SB1)
#define BUF1 (2 * SA1 + 2 * SB1)         // 46592
#define SMEM1 (2 * BUF1)                 // 93184

__global__ void __launch_bounds__(256, 1)
gemm1_mma(const float* __restrict__ bias)
{
    extern __shared__ char smem[];
    const uint32_t sb = smem_u32(smem);

    const int tid = threadIdx.x;
    const int l   = tid & 31;
    const int wid = tid >> 5;
    const int n   = blockIdx.z;
    const int p0  = blockIdx.x * 256;
    const int ho0 = p0 >> 7;
    const int wn  = wid * 32;

    const int a_row = ((l >> 3) & 1) * 8 + (l & 7);
    const int a_kb  = (l >> 4) * 8;
    const int b_kr  = ((l >> 3) & 1) * 8 + (l & 7);
    const int b_nb  = (l >> 4) * 8;

    float acc[5][4][4];
    #pragma unroll
    for (int i = 0; i < 5; ++i)
        #pragma unroll
        for (int j = 0; j < 4; ++j)
            #pragma unroll
            for (int q = 0; q < 4; ++q) acc[i][j][q] = 0.f;

    auto load_tile = [&](int kt, int b) {
        uint32_t base = sb + b * BUF1;
        // A: 320 16B-chunks per plane
        #pragma unroll
        for (int i = 0; i < 2; ++i) {
            int c = tid + i * 256;
            if (c < 320) {
                int r = c >> 2, j = c & 3;
                uint32_t dst = base + r * A1_PITCH + j * 16;
                cp16(dst + OFF_A1H, g_A1_hi + (size_t)r * KDIM + kt + j * 8);
                cp16(dst + OFF_A1L, g_A1_lo + (size_t)r * KDIM + kt + j * 8);
            }
        }
        // B: 1024 16B-chunks per plane (32 k-rows x 512B)
        #pragma unroll
        for (int i = 0; i < 4; ++i) {
            int c  = tid + i * 256;
            int r  = c >> 5;            // k-row 0..31
            int ch = c & 31;            // 16B chunk in row
            int j  = kt + r;
            int ci = j / 9;
            int kk = j - ci * 9;
            int ky = kk / 3;
            int kx = kk - ky * 3;
            int y  = ho0 + (ch >> 4) + 2 * ky;
            size_t src = (size_t)kx * XPLANE
                       + (((size_t)n * C_IN + ci) * H_IN + y) * 128 + (ch & 15) * 8;
            uint32_t dst = base + r * B1_PITCH + ch * 16;
            cp16(dst + OFF_B1H, g_X_hi + src);
            cp16(dst + OFF_B1L, g_X_lo + src);
        }
        CP_COMMIT();
    };

    load_tile(0, 0);

    for (int t = 0; t < NT; ++t) {
        int b = t & 1;
        if (t + 1 < NT) {
            load_tile((t + 1) * BK, b ^ 1);
            CP_WAIT(1);
        } else {
            CP_WAIT(0);
        }
        __syncthreads();

        uint32_t base = sb + b * BUF1;
        #pragma unroll
        for (int k16 = 0; k16 < BK; k16 += 16) {
            uint32_t ah[5][4], bh[4][2], bl[4][2];
            #pragma unroll
            for (int mt = 0; mt < 5; ++mt)
                ldsm_x4(ah[mt], base + OFF_A1H + (mt * 16 + a_row) * A1_PITCH
                                + (k16 + a_kb) * 2);
            #pragma unroll
            for (int nt2 = 0; nt2 < 2; ++nt2) {
                uint32_t r[4];
                ldsm_x4t(r, base + OFF_B1H + (k16 + b_kr) * B1_PITCH
                            + (wn + nt2 * 16 + b_nb) * 2);
                bh[nt2*2][0] = r[0]; bh[nt2*2][1] = r[1];
                bh[nt2*2+1][0] = r[2]; bh[nt2*2+1][1] = r[3];
            }
            #pragma unroll
            for (int mt = 0; mt < 5; ++mt)
                #pragma unroll
                for (int nt = 0; nt < 4; ++nt)
                    mma_bf16(acc[mt][nt], ah[mt], bh[nt]);
            #pragma unroll
            for (int nt2 = 0; nt2 < 2; ++nt2) {
                uint32_t r[4];
                ldsm_x4t(r, base + OFF_B1L + (k16 + b_kr) * B1_PITCH
                            + (wn + nt2 * 16 + b_nb) * 2);
                bl[nt2*2][0] = r[0]; bl[nt2*2][1] = r[1];
                bl[nt2*2+1][0] = r[2]; bl[nt2*2+1][1] = r[3];
            }
            #pragma unroll
            for (int mt = 0; mt < 5; ++mt)
                #pragma unroll
                for (int nt = 0; nt < 4; ++nt)
                    mma_bf16(acc[mt][nt], ah[mt], bl[nt]);
            #pragma unroll
            for (int mt = 0; mt < 5; ++mt) {
                uint32_t al[4];
                ldsm_x4(al, base + OFF_A1L + (mt * 16 + a_row) * A1_PITCH
                            + (k16 + a_kb) * 2);
                #pragma unroll
                for (int nt = 0; nt < 4; ++nt)
                    mma_bf16(acc[mt][nt], al, bh[nt]);
            }
        }
        __syncthreads();
    }

    // epilogue: rows 0..71, add bias
    float* ob = g_off + (size_t)n * M_OFF * NP + p0 + wn;
    #pragma unroll
    for (int mt = 0; mt < 5; ++mt) {
        int row = mt * 16 + (l >> 2);
        float bv0 = bias[row];
        #pragma unroll
        for (int nt = 0; nt < 4; ++nt) {
            int col = nt * 8 + (l & 3) * 2;
            float* p = ob + (size_t)row * NP + col;
            *reinterpret_cast<float2*>(p) =
                make_float2(acc[mt][nt][0] + bv0, acc[mt][nt][1] + bv0);
        }
        if (mt < 4) {
            float bv1 = bias[row + 8];
            #pragma unroll
            for (int nt = 0; nt < 4; ++nt) {
                int col = nt * 8 + (l & 3) * 2;
                float* p = ob + (size_t)(row + 8) * NP + col;
                *reinterpret_cast<float2*>(p) =
                    make_float2(acc[mt][nt][2] + bv1, acc[mt][nt][3] + bv1);
            }
        }
    }
}

// ================= gather: bilinear sample, 2 pixels/thread =================
__global__ void gather_sampled(const float* __restrict__ x) {
    int n  = blockIdx.z;
    int gk = blockIdx.y;
    int g  = gk / KKN, k = gk % KKN;
    int p  = (blockIdx.x * blockDim.x + threadIdx.x) * 2;
    int ho = p >> 7;
    int ky = k / 3, kx = k % 3;

    const float* offbase = g_off + ((size_t)n * M_OFF + g * 18 + k * 2) * NP + p;
    float2 dy = *reinterpret_cast<const float2*>(offbase);
    float2 dx = *reinterpret_cast<const float2*>(offbase + NP);

    float w00[2], w01[2], w10[2], w11[2];
    int i00[2], i01[2], i10[2], i11[2];
    #pragma unroll
    for (int s = 0; s < 2; ++s) {
        int wo = (p + s) & 127;
        float yf = (s ? dy.y : dy.x) + (float)(ky * 2 + ho);
        float xf = (s ? dx.y : dx.x) + (float)(kx * 2 + wo);
        float y0f = floorf(yf), x0f = floorf(xf);
        float ly = yf - y0f, lx = xf - x0f;
        int y0 = (int)y0f, x0 = (int)x0f;
        int y1 = y0 + 1,  x1 = x0 + 1;

        float a = (1.f - ly) * (1.f - lx);
        float b = (1.f - ly) * lx;
        float c = ly * (1.f - lx);
        float d = ly * lx;

        bool vy0 = (y0 >= 0) & (y0 < H_IN);
        bool vy1 = (y1 >= 0) & (y1 < H_IN);
        bool vx0 = (x0 >= 0) & (x0 < W_IN);
        bool vx1 = (x1 >= 0) & (x1 < W_IN);
        w00[s] = a * (float)(vy0 & vx0);
        w01[s] = b * (float)(vy0 & vx1);
        w10[s] = c * (float)(vy1 & vx0);
        w11[s] = d * (float)(vy1 & vx1);

        int cy0 = min(max(y0, 0), H_IN - 1);
        int cy1 = min(max(y1, 0), H_IN - 1);
        int cx0 = min(max(x0, 0), W_IN - 1);
        int cx1 = min(max(x1, 0), W_IN - 1);
        i00[s] = cy0 * W_IN + cx0;
        i01[s] = cy0 * W_IN + cx1;
        i10[s] = cy1 * W_IN + cx0;
        i11[s] = cy1 * W_IN + cx1;
    }

    const float* xb = x + ((size_t)n * C_IN + g * CG) * (H_IN * W_IN);
    size_t base = ((size_t)n * KDIM + (size_t)(g * KKN + k) * CG) * NP + p;
    __nv_bfloat16* hib = g_S_hi + base;
    __nv_bfloat16* lob = g_S_lo + base;

    #pragma unroll 2
    for (int c = 0; c < CG; ++c) {
        const float* xc = xb + c * (H_IN * W_IN);
        float v0 = w00[0] * __ldg(xc + i00[0]) + w01[0] * __ldg(xc + i01[0])
                 + w10[0] * __ldg(xc + i10[0]) + w11[0] * __ldg(xc + i11[0]);
        float v1 = w00[1] * __ldg(xc + i00[1]) + w01[1] * __ldg(xc + i01[1])
                 + w10[1] * __ldg(xc + i10[1]) + w11[1] * __ldg(xc + i11[1]);
        __nv_bfloat162 hp = __floats2bfloat162_rn(v0, v1);
        float r0 = v0 - __bfloat162float(hp.x);
        float r1 = v1 - __bfloat162float(hp.y);
        __nv_bfloat162 lp = __floats2bfloat162_rn(r0, r1);
        *reinterpret_cast<uint32_t*>(hib + (size_t)c * NP) = *reinterpret_cast<uint32_t*>(&hp);
        *reinterpret_cast<uint32_t*>(lob + (size_t)c * NP) = *reinterpret_cast<uint32_t*>(&lp);
    }
}

// ================= GEMM2: HMMA bf16, 3-term split, ldsm reuse =================
#define A_PITCH 80
#define B_PITCH 272
#define SA_PLANE (128 * A_PITCH)
#define SB_PLANE (32 * B_PITCH)
#define OFF_AH 0
#define OFF_AL SA_PLANE
#define OFF_BH (2 * SA_PLANE)
#define OFF_BL (2 * SA_PLANE + SB_PLANE)
#define BUF_BYTES (2 * SA_PLANE + 2 * SB_PLANE)
#define SMEM2_BYTES (2 * BUF_BYTES)

__global__ void __launch_bounds__(256, 2)
gemm2_mma(float* __restrict__ out)
{
    extern __shared__ char smem[];
    const uint32_t sb = smem_u32(smem);

    const int tid = threadIdx.x;
    const int wid = tid >> 5;
    const int l   = tid & 31;

    const int my = blockIdx.x;
    const int bx = blockIdx.y;
    const int n  = blockIdx.z;

    const int wm = (wid & 1) * 64;
    const int wn = (wid >> 1) * 32;

    const __nv_bfloat16* Ah = g_A_hi + (size_t)my * 128 * KDIM;
    const __nv_bfloat16* Al = g_A_lo + (size_t)my * 128 * KDIM;
    const __nv_bfloat16* Sh = g_S_hi + (size_t)n * KDIM * NP + (size_t)bx * 128;
    const __nv_bfloat16* Sl = g_S_lo + (size_t)n * KDIM * NP + (size_t)bx * 128;

    const int a_row = ((l >> 3) & 1) * 8 + (l & 7);
    const int a_kb  = (l >> 4) * 8;
    const int b_kr  = ((l >> 3) & 1) * 8 + (l & 7);
    const int b_nb  = (l >> 4) * 8;

    float acc[4][4][4];
    #pragma unroll
    for (int i = 0; i < 4; ++i)
        #pragma unroll
        for (int j = 0; j < 4; ++j)
            #pragma unroll
            for (int q = 0; q < 4; ++q) acc[i][j][q] = 0.f;

    auto load_tile = [&](int kt, int b) {
        uint32_t base = sb + b * BUF_BYTES;
        #pragma unroll
        for (int i = 0; i < 2; ++i) {
            int c = tid + i * 256;
            int r = c >> 2, j = c & 3;
            uint32_t dst = base + r * A_PITCH + j * 16;
            cp16(dst + OFF_AH, Ah + (size_t)r * KDIM + kt + j * 8);
            cp16(dst + OFF_AL, Al + (size_t)r * KDIM + kt + j * 8);
        }
        #pragma unroll
        for (int i = 0; i < 2; ++i) {
            int c = tid + i * 256;
            int r = c >> 4, j = c & 15;
            uint32_t dst = base + r * B_PITCH + j * 16;
            cp16(dst + OFF_BH, Sh + (size_t)(kt + r) * NP + j * 8);
            cp16(dst + OFF_BL, Sl + (size_t)(kt + r) * NP + j * 8);
        }
        CP_COMMIT();
    };

    load_tile(0, 0);

    for (int t = 0; t < NT; ++t) {
        int b = t & 1;
        if (t + 1 < NT) {
            load_tile((t + 1) * BK, b ^ 1);
            CP_WAIT(1);
        } else {
            CP_WAIT(0);
        }
        __syncthreads();

        uint32_t base = sb + b * BUF_BYTES;
        #pragma unroll
        for (int k16 = 0; k16 < BK; k16 += 16) {
            uint32_t ah[4][4], bh[4][2], bl[4][2];
            #pragma unroll
            for (int mt = 0; mt < 4; ++mt)
                ldsm_x4(ah[mt], base + OFF_AH + (wm + mt * 16 + a_row) * A_PITCH
                                + (k16 + a_kb) * 2);
            #pragma unroll
            for (int nt2 = 0; nt2 < 2; ++nt2) {
                uint32_t r[4];
                ldsm_x4t(r, base + OFF_BH + (k16 + b_kr) * B_PITCH
                            + (wn + nt2 * 16 + b_nb) * 2);
                bh[nt2*2][0] = r[0]; bh[nt2*2][1] = r[1];
                bh[nt2*2+1][0] = r[2]; bh[nt2*2+1][1] = r[3];
            }
            #pragma unroll
            for (int mt = 0; mt < 4; ++mt)
                #pragma unroll
                for (int nt = 0; nt < 4; ++nt)
                    mma_bf16(acc[mt][nt], ah[mt], bh[nt]);
            #pragma unroll
            for (int nt2 = 0; nt2 < 2; ++nt2) {
                uint32_t r[4];
                ldsm_x4t(r, base + OFF_BL + (k16 + b_kr) * B_PITCH
                            + (wn + nt2 * 16 + b_nb) * 2);
                bl[nt2*2][0] = r[0]; bl[nt2*2][1] = r[1];
                bl[nt2*2+1][0] = r[2]; bl[nt2*2+1][1] = r[3];
            }
            #pragma unroll
            for (int mt = 0; mt < 4; ++mt)
                #pragma unroll
                for (int nt = 0; nt < 4; ++nt)
                    mma_bf16(acc[mt][nt], ah[mt], bl[nt]);
            #pragma unroll
            for (int mt = 0; mt < 4; ++mt) {
                uint32_t al[4];
                ldsm_x4(al, base + OFF_AL + (wm + mt * 16 + a_row) * A_PITCH
                            + (k16 + a_kb) * 2);
                #pragma unroll
                for (int nt = 0; nt < 4; ++nt)
                    mma_bf16(acc[mt][nt], al, bh[nt]);
            }
        }
        __syncthreads();
    }

    float* ob = out + ((size_t)n * M_OUT + my * 128 + wm) * NP + (size_t)bx * 128 + wn;
    #pragma unroll
    for (int mt = 0; mt < 4; ++mt) {
        #pragma unroll
        for (int nt = 0; nt < 4; ++nt) {
            int row = mt * 16 + (l >> 2);
            int col = nt * 8 + (l & 3) * 2;
            float* p0 = ob + (size_t)row * NP + col;
            *reinterpret_cast<float2*>(p0) =
                make_float2(acc[mt][nt][0], acc[mt][nt][1]);
            *reinterpret_cast<float2*>(p0 + 8 * NP) =
                make_float2(acc[mt][nt][2], acc[mt][nt][3]);
        }
    }
}

// ---------------- launch ----------------
extern "C" void kernel_launch(void* const* d_in, const int* in_sizes, int n_in,
                              void* d_out, int out_size) {
    const float* x    = (const float*)d_in[0];
    const float* offw = (const float*)d_in[1];
    const float* offb = (const float*)d_in[2];
    const float* dw   = (const float*)d_in[3];
    float* out = (float*)d_out;

    cudaFuncSetAttribute(gemm1_mma, cudaFuncAttributeMaxDynamicSharedMemorySize, SMEM1);
    cudaFuncSetAttribute(gemm2_mma, cudaFuncAttributeMaxDynamicSharedMemorySize, SMEM2_BYTES);

    prep_w <<<(M_OUT * KDIM + 255) / 256, 256>>>(dw);
    prep_w1<<<(M_PAD * KDIM + 255) / 256, 256>>>(offw);
    prep_x <<<(int)((XPLANE + 255) / 256), 256>>>(x);
    // 1) offsets via tensor cores (pure cp.async im2col of pre-split x)
    {
        dim3 grid(NP / 256, 1, N_B);
        gemm1_mma<<<grid, 256, SMEM1>>>(offb);
    }
    // 2) bilinear sampled matrix -> bf16 hi/lo planes (2 px/thread)
    {
        dim3 grid(NP / 512, GRP * KKN, N_B);
        gather_sampled<<<grid, 256>>>(x);
    }
    // 3) out = dw @ sampled
    {
        dim3 grid(2, NP / 128, N_B);
        gemm2_mma<<<grid, 256, SMEM2_BYTES>>>(out);
    }
}